// round 15
// baseline (speedup 1.0000x reference)
#include <cuda_runtime.h>
#include <cuda_fp16.h>
#include <math.h>
#include <stdint.h>

#define MAXN 50000
#define MAXE 800000

// ---- scratch (device globals; no allocation allowed) ----
__device__ float g_deg1[MAXN];
__device__ int   g_cnt1[MAXN];
__device__ int   g_deg2[MAXN];
__device__ int   g_off1[MAXN + 1];
__device__ int   g_off2[MAXN + 1];
__device__ int   g_cur1[MAXN];
__device__ int   g_cur2[MAXN];
__device__ int2  g_pair1[MAXE];
__device__ int2  g_pair2[MAXE];
__device__ __half g_embh[(size_t)MAXN * 128];
__device__ float g_agg1[(size_t)MAXN * 128];
__device__ float g_x1[(size_t)MAXN * 256];
__device__ __half g_h2h[(size_t)MAXN * 128];
__device__ float g_x2[(size_t)MAXN * 128];
__device__ __half g_Adec[(size_t)MAXN * 128];
__device__ __half g_Bdec[(size_t)MAXN * 128];

__device__ __forceinline__ unsigned h2_bits(__half2 h) {
    unsigned u;
    *(__half2*)&u = h;
    return u;
}
__device__ __forceinline__ __half2 bits_h2(unsigned u) {
    return *(__half2*)&u;
}
__device__ __forceinline__ uint32_t smem_u32(const void* p) {
    uint32_t a;
    asm("{ .reg .u64 t; cvta.to.shared.u64 t, %1; cvt.u32.u64 %0, t; }" : "=r"(a) : "l"(p));
    return a;
}

// ================= fused zero-init + emb fp16 conversion =================
__global__ void init_f2h_kernel(const float* __restrict__ emb, __half* __restrict__ embh,
                                int N, int n4) {
    int i = blockIdx.x * blockDim.x + threadIdx.x;
    if (i < N) {
        g_deg1[i] = 0.f; g_cnt1[i] = 0; g_deg2[i] = 0;
        g_cur1[i] = 0; g_cur2[i] = 0;
    }
    for (int j = i; j < n4; j += gridDim.x * blockDim.x) {
        float4 v = ((const float4*)emb)[j];
        uint2 o;
        o.x = h2_bits(__floats2half2_rn(v.x, v.y));
        o.y = h2_bits(__floats2half2_rn(v.z, v.w));
        ((uint2*)embh)[j] = o;
    }
}

// ================= CSR build =================
__global__ void deg_cnt_kernel(const int* __restrict__ ei, const float* __restrict__ w,
                               const int* __restrict__ nei, int E) {
    int e = blockIdx.x * blockDim.x + threadIdx.x;
    if (e < E) {
        int c1 = ei[E + e];
        atomicAdd(&g_deg1[c1], w[e]);
        atomicAdd(&g_cnt1[c1], 1);
        atomicAdd(&g_deg2[nei[E + e]], 1);
    }
}

__global__ __launch_bounds__(1024, 1)
void scan2_kernel(int N, int E) {
    __shared__ int warpTot[32];
    int tid = threadIdx.x;
    int lane = tid & 31, w = tid >> 5;
    int chunk = (N + 1023) / 1024;
    int beg = tid * chunk;
    int end = beg + chunk; if (end > N) end = N;
#pragma unroll 1
    for (int a = 0; a < 2; a++) {
        const int* c = a ? g_deg2 : g_cnt1;
        int* o = a ? g_off2 : g_off1;
        __syncthreads();
        int t = 0;
        for (int i = beg; i < end; i++) t += c[i];
        int v = t;
#pragma unroll
        for (int d = 1; d < 32; d <<= 1) {
            int u = __shfl_up_sync(0xffffffffu, v, d);
            if (lane >= d) v += u;
        }
        if (lane == 31) warpTot[w] = v;
        __syncthreads();
        if (w == 0) {
            int x = warpTot[lane];
#pragma unroll
            for (int d = 1; d < 32; d <<= 1) {
                int u = __shfl_up_sync(0xffffffffu, x, d);
                if (lane >= d) x += u;
            }
            warpTot[lane] = x;
        }
        __syncthreads();
        int run = v - t + (w > 0 ? warpTot[w - 1] : 0);
        for (int i = beg; i < end; i++) { o[i] = run; run += c[i]; }
    }
    if (tid == 0) { g_off1[N] = E; g_off2[N] = E; }
}

__global__ void fill_kernel(const int* __restrict__ ei, const int* __restrict__ nei,
                            const float* __restrict__ w, const int* __restrict__ node_ids,
                            int E) {
    int e = blockIdx.x * blockDim.x + threadIdx.x;
    if (e >= E) return;
    {
        int r = ei[e], c = ei[E + e];
        float dr = g_deg1[r], dc = g_deg1[c];
        float nrm = (dr > 0.f ? rsqrtf(dr) : 0.f) * w[e] * (dc > 0.f ? rsqrtf(dc) : 0.f);
        int p = g_off1[c] + atomicAdd(&g_cur1[c], 1);
        g_pair1[p] = make_int2(node_ids[r], __float_as_int(nrm));
    }
    {
        int r = nei[e], c = nei[E + e];
        float dr = (float)g_deg2[r], dc = (float)g_deg2[c];
        float nrm = (dr > 0.f ? rsqrtf(dr) : 0.f) * (dc > 0.f ? rsqrtf(dc) : 0.f);
        int p = g_off2[c] + atomicAdd(&g_cur2[c], 1);
        g_pair2[p] = make_int2(r, __float_as_int(nrm));
    }
}

// ---- gather-reduce from fp16 rows, unroll-4 for MLP ----
__global__ void gather_f16_kernel(const __half* __restrict__ h, float* __restrict__ out,
                                  const int* __restrict__ off, const int2* __restrict__ pair,
                                  int N) {
    int gw = (blockIdx.x * blockDim.x + threadIdx.x) >> 5;
    if (gw >= N) return;
    int lane = threadIdx.x & 31;
    int s = off[gw], t = off[gw + 1];
    float4 acc0 = make_float4(0.f, 0.f, 0.f, 0.f);
    float4 acc1 = make_float4(0.f, 0.f, 0.f, 0.f);
    int i = s;
#define GF16_STEP(P, W, ACC)                                                   \
    {                                                                          \
        float nn = __int_as_float((P).y);                                      \
        float2 va = __half22float2(bits_h2((W).x));                            \
        float2 vb = __half22float2(bits_h2((W).y));                            \
        ACC.x = fmaf(va.x, nn, ACC.x); ACC.y = fmaf(va.y, nn, ACC.y);          \
        ACC.z = fmaf(vb.x, nn, ACC.z); ACC.w = fmaf(vb.y, nn, ACC.w);          \
    }
    for (; i + 4 <= t; i += 4) {
        int2 p0 = __ldg(pair + i), p1 = __ldg(pair + i + 1);
        int2 p2 = __ldg(pair + i + 2), p3 = __ldg(pair + i + 3);
        uint2 w0 = *(const uint2*)(h + (size_t)p0.x * 128 + lane * 4);
        uint2 w1 = *(const uint2*)(h + (size_t)p1.x * 128 + lane * 4);
        uint2 w2 = *(const uint2*)(h + (size_t)p2.x * 128 + lane * 4);
        uint2 w3 = *(const uint2*)(h + (size_t)p3.x * 128 + lane * 4);
        GF16_STEP(p0, w0, acc0) GF16_STEP(p1, w1, acc1)
        GF16_STEP(p2, w2, acc0) GF16_STEP(p3, w3, acc1)
    }
    for (; i + 2 <= t; i += 2) {
        int2 p0 = __ldg(pair + i), p1 = __ldg(pair + i + 1);
        uint2 w0 = *(const uint2*)(h + (size_t)p0.x * 128 + lane * 4);
        uint2 w1 = *(const uint2*)(h + (size_t)p1.x * 128 + lane * 4);
        GF16_STEP(p0, w0, acc0) GF16_STEP(p1, w1, acc1)
    }
    if (i < t) {
        int2 p0 = __ldg(pair + i);
        uint2 w0 = *(const uint2*)(h + (size_t)p0.x * 128 + lane * 4);
        GF16_STEP(p0, w0, acc0)
    }
#undef GF16_STEP
    acc0.x += acc1.x; acc0.y += acc1.y; acc0.z += acc1.z; acc0.w += acc1.w;
    *(float4*)(out + (size_t)gw * 128 + lane * 4) = acc0;
}

// ================= fp16 mma.sync node GEMM (m16n8k16, hi/lo split) =================
// Software-prefetched K loop: global loads for iteration kt+32 issue before the
// mma section of iteration kt, overlapping load latency with tensor work.
#define A_STU 20   // u32 per A row (40 halves, 80 bytes)
#define W_STU 21   // u32 per W^T row (42 halves, 84 bytes)

template <int SPLIT, int PREACT, int DUAL, int OUTH>
__global__ __launch_bounds__(256, 2)
void gemm_fp16_kernel(const float* __restrict__ A, const float* __restrict__ W,
                      void* __restrict__ C, int M, int K, int Nc,
                      const float* __restrict__ bias, int act,
                      const float* __restrict__ abias,
                      const float* __restrict__ Wb, void* __restrict__ Cb) {
    extern __shared__ unsigned smg[];
    unsigned* Ahu = smg;
    unsigned* Alu = Ahu + 128 * A_STU;
    unsigned* Whu = Alu + (SPLIT ? 128 * A_STU : 0);
    unsigned* Wlu = Whu + 128 * W_STU;

    int tid = threadIdx.x;
    int warp = tid >> 5, lane = tid & 31;
    int qr = lane >> 2, qc = lane & 3;
    int m0 = blockIdx.y * 128;
    const float* Wp = W;
    void* Cp = C;
    int n0 = blockIdx.x * 128;
    if (DUAL) {
        if (blockIdx.x) { Wp = Wb; Cp = Cb; }
        n0 = 0;
    }
    int r0 = warp * 16;

    uint32_t Ah_s = smem_u32(Ahu);
    uint32_t Al_s = smem_u32(Alu);
    int laneRow = (lane & 7) + (lane & 8);
    int laneColB = ((lane >> 4) & 1) * 16;
    uint32_t lmH = Ah_s + (uint32_t)(r0 + laneRow) * 80 + (uint32_t)laneColB;
    uint32_t lmL = Al_s + (uint32_t)(r0 + laneRow) * 80 + (uint32_t)laneColB;

    // per-thread staging coordinates (A: 4 loads; W: 2 loads)
    int aRow[4], aCol[4];
#pragma unroll
    for (int i = 0; i < 4; i++) {
        int idx4 = tid + i * 256;
        aRow[i] = idx4 >> 3;
        aCol[i] = (idx4 & 7) << 2;
    }
    int wK2[2], wN[2];
#pragma unroll
    for (int i = 0; i < 2; i++) {
        int idx4 = tid + i * 256;
        wK2[i] = idx4 >> 5;
        wN[i] = (idx4 & 31) << 2;
    }

    float4 vA[4], vWa[2], vWb[2];
#define LOAD_TILE(KT)                                                           \
    {                                                                           \
        _Pragma("unroll")                                                       \
        for (int i = 0; i < 4; i++) {                                           \
            vA[i] = make_float4(0.f, 0.f, 0.f, 0.f);                            \
            if (m0 + aRow[i] < M)                                               \
                vA[i] = *(const float4*)(A + (size_t)(m0 + aRow[i]) * K + (KT) + aCol[i]); \
        }                                                                       \
        _Pragma("unroll")                                                       \
        for (int i = 0; i < 2; i++) {                                           \
            const float* wp0 = Wp + (size_t)((KT) + 2 * wK2[i]) * Nc + n0 + wN[i]; \
            vWa[i] = *(const float4*)wp0;                                       \
            vWb[i] = *(const float4*)(wp0 + Nc);                                \
        }                                                                       \
    }

    float acc[16][4];
#pragma unroll
    for (int n = 0; n < 16; n++)
#pragma unroll
        for (int j = 0; j < 4; j++) acc[n][j] = 0.f;

    LOAD_TILE(0);

    for (int kt = 0; kt < K; kt += 32) {
        // stage A from registers
#pragma unroll
        for (int i = 0; i < 4; i++) {
            float4 v = vA[i];
            if (PREACT) {
                float4 ab = *(const float4*)(abias + kt + aCol[i]);
                v.x += ab.x; v.y += ab.y; v.z += ab.z; v.w += ab.w;
                v.x = v.x > 0.f ? v.x : expm1f(v.x);
                v.y = v.y > 0.f ? v.y : expm1f(v.y);
                v.z = v.z > 0.f ? v.z : expm1f(v.z);
                v.w = v.w > 0.f ? v.w : expm1f(v.w);
            }
            __half h0 = __float2half_rn(v.x), h1 = __float2half_rn(v.y);
            __half h2_ = __float2half_rn(v.z), h3 = __float2half_rn(v.w);
            int base = aRow[i] * A_STU + (aCol[i] >> 1);
            Ahu[base] = h2_bits(__halves2half2(h0, h1));
            Ahu[base + 1] = h2_bits(__halves2half2(h2_, h3));
            if (SPLIT) {
                __half l0 = __float2half_rn(v.x - __half2float(h0));
                __half l1 = __float2half_rn(v.y - __half2float(h1));
                __half l2 = __float2half_rn(v.z - __half2float(h2_));
                __half l3 = __float2half_rn(v.w - __half2float(h3));
                Alu[base] = h2_bits(__halves2half2(l0, l1));
                Alu[base + 1] = h2_bits(__halves2half2(l2, l3));
            }
        }
        // stage W from registers (transposed [n][k])
#pragma unroll
        for (int i = 0; i < 2; i++) {
            float fa[4] = {vWa[i].x, vWa[i].y, vWa[i].z, vWa[i].w};
            float fb[4] = {vWb[i].x, vWb[i].y, vWb[i].z, vWb[i].w};
#pragma unroll
            for (int j = 0; j < 4; j++) {
                __half ha = __float2half_rn(fa[j]), hb = __float2half_rn(fb[j]);
                Whu[(wN[i] + j) * W_STU + wK2[i]] = h2_bits(__halves2half2(ha, hb));
                if (SPLIT) {
                    __half la = __float2half_rn(fa[j] - __half2float(ha));
                    __half lb = __float2half_rn(fb[j] - __half2float(hb));
                    Wlu[(wN[i] + j) * W_STU + wK2[i]] = h2_bits(__halves2half2(la, lb));
                }
            }
        }
        __syncthreads();

        // prefetch next tile's globals (overlaps with mma below)
        if (kt + 32 < K) LOAD_TILE(kt + 32);

#pragma unroll
        for (int kk = 0; kk < 2; kk++) {
            unsigned ah0, ah1, ah2, ah3, al0, al1, al2, al3;
            asm volatile(
                "ldmatrix.sync.aligned.m8n8.x4.shared.b16 {%0,%1,%2,%3}, [%4];"
                : "=r"(ah0), "=r"(ah1), "=r"(ah2), "=r"(ah3)
                : "r"(lmH + (uint32_t)kk * 32));
            if (SPLIT) {
                asm volatile(
                    "ldmatrix.sync.aligned.m8n8.x4.shared.b16 {%0,%1,%2,%3}, [%4];"
                    : "=r"(al0), "=r"(al1), "=r"(al2), "=r"(al3)
                    : "r"(lmL + (uint32_t)kk * 32));
            }
#pragma unroll
            for (int nc = 0; nc < 16; nc++) {
                int widx = (nc * 8 + qr) * W_STU + kk * 8 + qc;
                unsigned bh0 = Whu[widx];
                unsigned bh1 = Whu[widx + 4];
                asm volatile(
                    "mma.sync.aligned.m16n8k16.row.col.f32.f16.f16.f32 "
                    "{%0,%1,%2,%3}, {%4,%5,%6,%7}, {%8,%9}, {%0,%1,%2,%3};"
                    : "+f"(acc[nc][0]), "+f"(acc[nc][1]), "+f"(acc[nc][2]), "+f"(acc[nc][3])
                    : "r"(ah0), "r"(ah1), "r"(ah2), "r"(ah3), "r"(bh0), "r"(bh1));
                if (SPLIT) {
                    unsigned bl0 = Wlu[widx];
                    unsigned bl1 = Wlu[widx + 4];
                    asm volatile(
                        "mma.sync.aligned.m16n8k16.row.col.f32.f16.f16.f32 "
                        "{%0,%1,%2,%3}, {%4,%5,%6,%7}, {%8,%9}, {%0,%1,%2,%3};"
                        : "+f"(acc[nc][0]), "+f"(acc[nc][1]), "+f"(acc[nc][2]), "+f"(acc[nc][3])
                        : "r"(ah0), "r"(ah1), "r"(ah2), "r"(ah3), "r"(bl0), "r"(bl1));
                    asm volatile(
                        "mma.sync.aligned.m16n8k16.row.col.f32.f16.f16.f32 "
                        "{%0,%1,%2,%3}, {%4,%5,%6,%7}, {%8,%9}, {%0,%1,%2,%3};"
                        : "+f"(acc[nc][0]), "+f"(acc[nc][1]), "+f"(acc[nc][2]), "+f"(acc[nc][3])
                        : "r"(al0), "r"(al1), "r"(al2), "r"(al3), "r"(bh0), "r"(bh1));
                }
            }
        }
        __syncthreads();
    }
#undef LOAD_TILE

    int row0 = m0 + r0 + qr;
    int row1 = row0 + 8;
#pragma unroll
    for (int nc = 0; nc < 16; nc++) {
        int c0 = n0 + nc * 8 + qc * 2;
        float bz0 = 0.f, bz1 = 0.f;
        if (bias) { bz0 = __ldg(bias + c0); bz1 = __ldg(bias + c0 + 1); }
        float u0 = acc[nc][0] + bz0, u1 = acc[nc][1] + bz1;
        float u2 = acc[nc][2] + bz0, u3 = acc[nc][3] + bz1;
        if (act) {
            u0 = u0 > 0.f ? u0 : expm1f(u0);
            u1 = u1 > 0.f ? u1 : expm1f(u1);
            u2 = u2 > 0.f ? u2 : expm1f(u2);
            u3 = u3 > 0.f ? u3 : expm1f(u3);
        }
        if (OUTH) {
            if (row0 < M) *(__half2*)((__half*)Cp + (size_t)row0 * Nc + c0) = __floats2half2_rn(u0, u1);
            if (row1 < M) *(__half2*)((__half*)Cp + (size_t)row1 * Nc + c0) = __floats2half2_rn(u2, u3);
        } else {
            if (row0 < M) *(float2*)((float*)Cp + (size_t)row0 * Nc + c0) = make_float2(u0, u1);
            if (row1 < M) *(float2*)((float*)Cp + (size_t)row1 * Nc + c0) = make_float2(u2, u3);
        }
    }
}

// ============================================================================
// Persistent fp16 edge decoder (mma.sync m16n8k16.f16, ldmatrix A-fragments,
// half2 phase-1, per-warp epilogue slices, next-tile index prefetch)
// ============================================================================
#define TS_HW 68   // u32 words per t row (136 halves; row stride 272 bytes)

__global__ __launch_bounds__(256, 3)
void decoder_fp16_kernel(const __half* __restrict__ Ad, const __half* __restrict__ Bd,
                         const int* __restrict__ ei,
                         const float* __restrict__ b1, const float* __restrict__ W2,
                         const float* __restrict__ b2, const float* __restrict__ W3,
                         const float* __restrict__ b3, float* __restrict__ out,
                         int E, int numTiles) {
    extern __shared__ unsigned smemd[];
    unsigned* tS = smemd;                           // 128 x TS_HW u32
    unsigned* b1h = smemd + 128 * TS_HW;            // 64 u32 (half2-packed b1)
    float* esum = (float*)(b1h + 64);               // 8 x 128 floats
    int tid = threadIdx.x;
    int warp = tid >> 5, lane = tid & 31;
    int qr = lane >> 2, qc = lane & 3;
    int nBase = warp * 16;
    uint32_t tS_s = smem_u32(tS);
    int laneRow = (lane & 7) + (lane & 8);
    int laneColB = ((lane >> 4) & 1) * 16;
    uint32_t lmBase = tS_s + (uint32_t)laneRow * 272 + (uint32_t)laneColB;
    float* esumW = esum + warp * 128;

    unsigned bf[8][2][2];
#pragma unroll
    for (int c = 0; c < 8; c++) {
        int kb = c * 16;
#pragma unroll
        for (int ncl = 0; ncl < 2; ncl++) {
            int n = nBase + ncl * 8 + qr;
            bf[c][ncl][0] = h2_bits(__floats2half2_rn(
                __ldg(W2 + (kb + 2 * qc) * 128 + n), __ldg(W2 + (kb + 2 * qc + 1) * 128 + n)));
            bf[c][ncl][1] = h2_bits(__floats2half2_rn(
                __ldg(W2 + (kb + 2 * qc + 8) * 128 + n), __ldg(W2 + (kb + 2 * qc + 9) * 128 + n)));
        }
    }
    float bb0[2], bb1[2], w30[2], w31[2];
#pragma unroll
    for (int ncl = 0; ncl < 2; ncl++) {
        int c0 = nBase + ncl * 8 + qc * 2;
        bb0[ncl] = __ldg(b2 + c0); bb1[ncl] = __ldg(b2 + c0 + 1);
        w30[ncl] = __ldg(W3 + c0); w31[ncl] = __ldg(W3 + c0 + 1);
    }
    float b3v = __ldg(b3);
    if (tid < 64) b1h[tid] = h2_bits(__floats2half2_rn(__ldg(b1 + 2 * tid), __ldg(b1 + 2 * tid + 1)));
    __syncthreads();

    const __half2 hz = __floats2half2_rn(0.f, 0.f);
    int eloc = tid >> 1;
    int half_ = tid & 1;

    // prefetch indices for first tile
    int sCur = 0, dCur = 0, vCur = 0;
    {
        int tile0 = blockIdx.x;
        if (tile0 < numTiles) {
            int e = tile0 * 128 + eloc;
            if (e < E) { sCur = ei[e]; dCur = ei[E + e]; vCur = 1; }
        }
    }

    for (int tile = blockIdx.x; tile < numTiles; tile += gridDim.x) {
        __syncthreads();

        // phase 1: t = relu(A[src]+B[dst]+b1) using prefetched indices
        {
            uint4* trow4 = (uint4*)(tS + eloc * TS_HW + half_ * 32);
            if (vCur) {
                const uint4* ap = (const uint4*)(Ad + (size_t)sCur * 128) + half_ * 8;
                const uint4* bp = (const uint4*)(Bd + (size_t)dCur * 128) + half_ * 8;
                const uint4* cb = (const uint4*)b1h + half_ * 8;
#pragma unroll
                for (int j = 0; j < 8; j++) {
                    uint4 av = __ldg(ap + j);
                    uint4 bv = __ldg(bp + j);
                    uint4 cv = cb[j];
                    uint4 r;
                    r.x = h2_bits(__hmax2(__hadd2(__hadd2(bits_h2(av.x), bits_h2(bv.x)), bits_h2(cv.x)), hz));
                    r.y = h2_bits(__hmax2(__hadd2(__hadd2(bits_h2(av.y), bits_h2(bv.y)), bits_h2(cv.y)), hz));
                    r.z = h2_bits(__hmax2(__hadd2(__hadd2(bits_h2(av.z), bits_h2(bv.z)), bits_h2(cv.z)), hz));
                    r.w = h2_bits(__hmax2(__hadd2(__hadd2(bits_h2(av.w), bits_h2(bv.w)), bits_h2(cv.w)), hz));
                    trow4[j] = r;
                }
            } else {
                uint4 z4 = make_uint4(0u, 0u, 0u, 0u);
#pragma unroll
                for (int j = 0; j < 8; j++) trow4[j] = z4;
            }
        }
        __syncthreads();

        // prefetch next tile's indices (overlaps with phase 2)
        {
            int tNext = tile + gridDim.x;
            vCur = 0;
            if (tNext < numTiles) {
                int e = tNext * 128 + eloc;
                if (e < E) { sCur = ei[e]; dCur = ei[E + e]; vCur = 1; }
            }
        }

#pragma unroll 1
        for (int m = 0; m < 8; m++) {
            int r0 = m * 16;
            uint32_t rowAddr = lmBase + (uint32_t)r0 * 272;
            float acc[2][4];
            acc[0][0] = acc[0][1] = acc[0][2] = acc[0][3] = 0.f;
            acc[1][0] = acc[1][1] = acc[1][2] = acc[1][3] = 0.f;
#pragma unroll
            for (int c = 0; c < 8; c++) {
                unsigned a0, a1, a2, a3;
                asm volatile(
                    "ldmatrix.sync.aligned.m8n8.x4.shared.b16 {%0,%1,%2,%3}, [%4];"
                    : "=r"(a0), "=r"(a1), "=r"(a2), "=r"(a3)
                    : "r"(rowAddr + (uint32_t)c * 32));
                asm volatile(
                    "mma.sync.aligned.m16n8k16.row.col.f32.f16.f16.f32 "
                    "{%0,%1,%2,%3}, {%4,%5,%6,%7}, {%8,%9}, {%0,%1,%2,%3};"
                    : "+f"(acc[0][0]), "+f"(acc[0][1]), "+f"(acc[0][2]), "+f"(acc[0][3])
                    : "r"(a0), "r"(a1), "r"(a2), "r"(a3), "r"(bf[c][0][0]), "r"(bf[c][0][1]));
                asm volatile(
                    "mma.sync.aligned.m16n8k16.row.col.f32.f16.f16.f32 "
                    "{%0,%1,%2,%3}, {%4,%5,%6,%7}, {%8,%9}, {%0,%1,%2,%3};"
                    : "+f"(acc[1][0]), "+f"(acc[1][1]), "+f"(acc[1][2]), "+f"(acc[1][3])
                    : "r"(a0), "r"(a1), "r"(a2), "r"(a3), "r"(bf[c][1][0]), "r"(bf[c][1][1]));
            }
            float e0 = 0.f, e1 = 0.f;
#pragma unroll
            for (int ncl = 0; ncl < 2; ncl++) {
                e0 += fmaxf(acc[ncl][0] + bb0[ncl], 0.f) * w30[ncl]
                    + fmaxf(acc[ncl][1] + bb1[ncl], 0.f) * w31[ncl];
                e1 += fmaxf(acc[ncl][2] + bb0[ncl], 0.f) * w30[ncl]
                    + fmaxf(acc[ncl][3] + bb1[ncl], 0.f) * w31[ncl];
            }
            e0 += __shfl_xor_sync(0xffffffffu, e0, 1);
            e0 += __shfl_xor_sync(0xffffffffu, e0, 2);
            e1 += __shfl_xor_sync(0xffffffffu, e1, 1);
            e1 += __shfl_xor_sync(0xffffffffu, e1, 2);
            if (qc == 0) {
                esumW[r0 + qr] = e0;
                esumW[r0 + qr + 8] = e1;
            }
        }
        __syncthreads();

        if (tid < 128) {
            int e = tile * 128 + tid;
            if (e < E) {
                float s = esum[tid];
#pragma unroll
                for (int w = 1; w < 8; w++) s += esum[w * 128 + tid];
                out[e] = s + b3v;
            }
        }
    }
}

extern "C" void kernel_launch(void* const* d_in, const int* in_sizes, int n_in,
                              void* d_out, int out_size) {
    const int* node_ids = (const int*)d_in[0];
    const int* ei       = (const int*)d_in[1];
    const int* nei      = (const int*)d_in[2];
    const float* eattr  = (const float*)d_in[3];
    const float* emb    = (const float*)d_in[4];
    const float* W_in   = (const float*)d_in[5];
    const float* b_in   = (const float*)d_in[6];
    const float* W_out  = (const float*)d_in[7];
    const float* b_out  = (const float*)d_in[8];
    const float* W1     = (const float*)d_in[9];
    const float* b1     = (const float*)d_in[10];
    const float* W2     = (const float*)d_in[11];
    const float* b2     = (const float*)d_in[12];
    const float* W3     = (const float*)d_in[13];
    const float* b3     = (const float*)d_in[14];
    int N = in_sizes[0];
    int E = in_sizes[3];
    float* out = (float*)d_out;

    float *agg1, *x1, *x2;
    __half *embh, *h2h, *Ad, *Bd;
    int *off1, *off2;
    int2 *pair1, *pair2;
    cudaGetSymbolAddress((void**)&embh, g_embh);
    cudaGetSymbolAddress((void**)&agg1, g_agg1);
    cudaGetSymbolAddress((void**)&x1, g_x1);
    cudaGetSymbolAddress((void**)&h2h, g_h2h);
    cudaGetSymbolAddress((void**)&x2, g_x2);
    cudaGetSymbolAddress((void**)&Ad, g_Adec);
    cudaGetSymbolAddress((void**)&Bd, g_Bdec);
    cudaGetSymbolAddress((void**)&off1, g_off1);
    cudaGetSymbolAddress((void**)&off2, g_off2);
    cudaGetSymbolAddress((void**)&pair1, g_pair1);
    cudaGetSymbolAddress((void**)&pair2, g_pair2);

    const int T = 256;
    init_f2h_kernel<<<(N * 32 + T - 1) / T, T>>>(emb, embh, N, N * 32);
    deg_cnt_kernel<<<(E + T - 1) / T, T>>>(ei, eattr, nei, E);
    scan2_kernel<<<1, 1024>>>(N, E);
    fill_kernel<<<(E + T - 1) / T, T>>>(ei, nei, eattr, node_ids, E);

    int mBlocks = (N + 127) / 128;
    int smem_split = (128 * A_STU * 2 + 128 * W_STU * 2) * 4;
    cudaFuncSetAttribute((const void*)gemm_fp16_kernel<1, 0, 0, 0>,
                         cudaFuncAttributeMaxDynamicSharedMemorySize, smem_split);
    cudaFuncSetAttribute((const void*)gemm_fp16_kernel<1, 0, 0, 1>,
                         cudaFuncAttributeMaxDynamicSharedMemorySize, smem_split);
    cudaFuncSetAttribute((const void*)gemm_fp16_kernel<1, 1, 1, 1>,
                         cudaFuncAttributeMaxDynamicSharedMemorySize, smem_split);

    int gatherBlocks = (N * 32 + T - 1) / T;

    // conv1: fp16 gather-aggregate emb, then fp16-split GEMM with fused bias+elu
    gather_f16_kernel<<<gatherBlocks, T>>>(embh, agg1, off1, pair1, N);
    gemm_fp16_kernel<1, 0, 0, 0><<<dim3(2, mBlocks), 256, smem_split>>>(
        agg1, W_in, x1, N, 128, 256, b_in, 1, nullptr, nullptr, nullptr);

    // conv2: fp16-split GEMM (fp16 out) then fp16 gather-aggregate
    gemm_fp16_kernel<1, 0, 0, 1><<<dim3(1, mBlocks), 256, smem_split>>>(
        x1, W_out, h2h, N, 256, 128, nullptr, 0, nullptr, nullptr, nullptr);
    gather_f16_kernel<<<gatherBlocks, T>>>(h2h, x2, off2, pair2, N);

    // merged dual pre-GEMMs (fp16 split; elu(x2+b_out) fused on A, fp16 outputs)
    gemm_fp16_kernel<1, 1, 1, 1><<<dim3(2, mBlocks), 256, smem_split>>>(
        x2, W1, Ad, N, 128, 128, nullptr, 0, b_out, W1 + 128 * 128, Bd);

    // persistent fp16 tensor-core edge decoder
    int numTiles = (E + 127) / 128;
    int smem_dec = (128 * TS_HW + 64 + 8 * 128) * 4;
    cudaFuncSetAttribute(decoder_fp16_kernel, cudaFuncAttributeMaxDynamicSharedMemorySize, smem_dec);
    int grid_dec = 3 * 148;
    if (grid_dec > numTiles) grid_dec = numTiles;
    decoder_fp16_kernel<<<grid_dec, 256, smem_dec>>>(Ad, Bd, ei, b1, W2, b2, W3, b3, out, E, numTiles);
}

// round 16
// speedup vs baseline: 1.0088x; 1.0088x over previous
#include <cuda_runtime.h>
#include <cuda_fp16.h>
#include <math.h>
#include <stdint.h>

#define MAXN 50000
#define MAXE 800000

// ---- scratch (device globals; no allocation allowed) ----
__device__ float g_deg1[MAXN];
__device__ int   g_cnt1[MAXN];
__device__ int   g_deg2[MAXN];
__device__ int   g_off1[MAXN + 1];
__device__ int   g_off2[MAXN + 1];
__device__ int   g_rank1[MAXE];
__device__ int   g_rank2[MAXE];
__device__ int2  g_pair1[MAXE];
__device__ int2  g_pair2[MAXE];
__device__ __half g_embh[(size_t)MAXN * 128];
__device__ float g_agg1[(size_t)MAXN * 128];
__device__ float g_x1[(size_t)MAXN * 256];
__device__ __half g_h2h[(size_t)MAXN * 128];
__device__ float g_x2[(size_t)MAXN * 128];
__device__ __half g_Adec[(size_t)MAXN * 128];
__device__ __half g_Bdec[(size_t)MAXN * 128];

__device__ __forceinline__ unsigned h2_bits(__half2 h) {
    unsigned u;
    *(__half2*)&u = h;
    return u;
}
__device__ __forceinline__ __half2 bits_h2(unsigned u) {
    return *(__half2*)&u;
}
__device__ __forceinline__ uint32_t smem_u32(const void* p) {
    uint32_t a;
    asm("{ .reg .u64 t; cvta.to.shared.u64 t, %1; cvt.u32.u64 %0, t; }" : "=r"(a) : "l"(p));
    return a;
}

// ================= fused zero-init + emb fp16 conversion =================
__global__ void init_f2h_kernel(const float* __restrict__ emb, __half* __restrict__ embh,
                                int N, int n4) {
    int i = blockIdx.x * blockDim.x + threadIdx.x;
    if (i < N) {
        g_deg1[i] = 0.f; g_cnt1[i] = 0; g_deg2[i] = 0;
    }
    for (int j = i; j < n4; j += gridDim.x * blockDim.x) {
        float4 v = ((const float4*)emb)[j];
        uint2 o;
        o.x = h2_bits(__floats2half2_rn(v.x, v.y));
        o.y = h2_bits(__floats2half2_rn(v.z, v.w));
        ((uint2*)embh)[j] = o;
    }
}

// ================= CSR build =================
// deg_cnt also records each edge's rank within its destination bucket, so
// fill_kernel needs no atomics at all.
__global__ void deg_cnt_kernel(const int* __restrict__ ei, const float* __restrict__ w,
                               const int* __restrict__ nei, int E) {
    int e = blockIdx.x * blockDim.x + threadIdx.x;
    if (e < E) {
        int c1 = ei[E + e];
        atomicAdd(&g_deg1[c1], w[e]);
        g_rank1[e] = atomicAdd(&g_cnt1[c1], 1);
        g_rank2[e] = atomicAdd(&g_deg2[nei[E + e]], 1);
    }
}

__global__ __launch_bounds__(1024, 1)
void scan2_kernel(int N, int E) {
    __shared__ int warpTot[32];
    int tid = threadIdx.x;
    int lane = tid & 31, w = tid >> 5;
    int chunk = (N + 1023) / 1024;
    int beg = tid * chunk;
    int end = beg + chunk; if (end > N) end = N;
#pragma unroll 1
    for (int a = 0; a < 2; a++) {
        const int* c = a ? g_deg2 : g_cnt1;
        int* o = a ? g_off2 : g_off1;
        __syncthreads();
        int t = 0;
        for (int i = beg; i < end; i++) t += c[i];
        int v = t;
#pragma unroll
        for (int d = 1; d < 32; d <<= 1) {
            int u = __shfl_up_sync(0xffffffffu, v, d);
            if (lane >= d) v += u;
        }
        if (lane == 31) warpTot[w] = v;
        __syncthreads();
        if (w == 0) {
            int x = warpTot[lane];
#pragma unroll
            for (int d = 1; d < 32; d <<= 1) {
                int u = __shfl_up_sync(0xffffffffu, x, d);
                if (lane >= d) x += u;
            }
            warpTot[lane] = x;
        }
        __syncthreads();
        int run = v - t + (w > 0 ? warpTot[w - 1] : 0);
        for (int i = beg; i < end; i++) { o[i] = run; run += c[i]; }
    }
    if (tid == 0) { g_off1[N] = E; g_off2[N] = E; }
}

// atomic-free fill: slot = off[dst] + rank[e]
__global__ void fill_kernel(const int* __restrict__ ei, const int* __restrict__ nei,
                            const float* __restrict__ w, const int* __restrict__ node_ids,
                            int E) {
    int e = blockIdx.x * blockDim.x + threadIdx.x;
    if (e >= E) return;
    {
        int r = ei[e], c = ei[E + e];
        float dr = g_deg1[r], dc = g_deg1[c];
        float nrm = (dr > 0.f ? rsqrtf(dr) : 0.f) * w[e] * (dc > 0.f ? rsqrtf(dc) : 0.f);
        g_pair1[g_off1[c] + g_rank1[e]] = make_int2(node_ids[r], __float_as_int(nrm));
    }
    {
        int r = nei[e], c = nei[E + e];
        float dr = (float)g_deg2[r], dc = (float)g_deg2[c];
        float nrm = (dr > 0.f ? rsqrtf(dr) : 0.f) * (dc > 0.f ? rsqrtf(dc) : 0.f);
        g_pair2[g_off2[c] + g_rank2[e]] = make_int2(r, __float_as_int(nrm));
    }
}

// ---- gather-reduce from fp16 rows: half-warp (16 lanes) per node, uint4 lane loads ----
__global__ void gather_f16_kernel(const __half* __restrict__ h, float* __restrict__ out,
                                  const int* __restrict__ off, const int2* __restrict__ pair,
                                  int N) {
    int gw = (blockIdx.x * blockDim.x + threadIdx.x) >> 4;
    if (gw >= N) return;
    int lane = threadIdx.x & 15;
    int s = off[gw], t = off[gw + 1];
    float acc0[8] = {0.f, 0.f, 0.f, 0.f, 0.f, 0.f, 0.f, 0.f};
    float acc1[8] = {0.f, 0.f, 0.f, 0.f, 0.f, 0.f, 0.f, 0.f};
    int i = s;
#define GF16_STEP(P, W, ACC)                                                   \
    {                                                                          \
        float nn = __int_as_float((P).y);                                      \
        float2 v0 = __half22float2(bits_h2((W).x));                            \
        float2 v1 = __half22float2(bits_h2((W).y));                            \
        float2 v2 = __half22float2(bits_h2((W).z));                            \
        float2 v3 = __half22float2(bits_h2((W).w));                            \
        ACC[0] = fmaf(v0.x, nn, ACC[0]); ACC[1] = fmaf(v0.y, nn, ACC[1]);      \
        ACC[2] = fmaf(v1.x, nn, ACC[2]); ACC[3] = fmaf(v1.y, nn, ACC[3]);      \
        ACC[4] = fmaf(v2.x, nn, ACC[4]); ACC[5] = fmaf(v2.y, nn, ACC[5]);      \
        ACC[6] = fmaf(v3.x, nn, ACC[6]); ACC[7] = fmaf(v3.y, nn, ACC[7]);      \
    }
    for (; i + 4 <= t; i += 4) {
        int2 p0 = __ldg(pair + i), p1 = __ldg(pair + i + 1);
        int2 p2 = __ldg(pair + i + 2), p3 = __ldg(pair + i + 3);
        uint4 w0 = *(const uint4*)(h + (size_t)p0.x * 128 + lane * 8);
        uint4 w1 = *(const uint4*)(h + (size_t)p1.x * 128 + lane * 8);
        uint4 w2 = *(const uint4*)(h + (size_t)p2.x * 128 + lane * 8);
        uint4 w3 = *(const uint4*)(h + (size_t)p3.x * 128 + lane * 8);
        GF16_STEP(p0, w0, acc0) GF16_STEP(p1, w1, acc1)
        GF16_STEP(p2, w2, acc0) GF16_STEP(p3, w3, acc1)
    }
    for (; i + 2 <= t; i += 2) {
        int2 p0 = __ldg(pair + i), p1 = __ldg(pair + i + 1);
        uint4 w0 = *(const uint4*)(h + (size_t)p0.x * 128 + lane * 8);
        uint4 w1 = *(const uint4*)(h + (size_t)p1.x * 128 + lane * 8);
        GF16_STEP(p0, w0, acc0) GF16_STEP(p1, w1, acc1)
    }
    if (i < t) {
        int2 p0 = __ldg(pair + i);
        uint4 w0 = *(const uint4*)(h + (size_t)p0.x * 128 + lane * 8);
        GF16_STEP(p0, w0, acc0)
    }
#undef GF16_STEP
    float* o = out + (size_t)gw * 128 + lane * 8;
    *(float4*)o = make_float4(acc0[0] + acc1[0], acc0[1] + acc1[1],
                              acc0[2] + acc1[2], acc0[3] + acc1[3]);
    *(float4*)(o + 4) = make_float4(acc0[4] + acc1[4], acc0[5] + acc1[5],
                                    acc0[6] + acc1[6], acc0[7] + acc1[7]);
}

// ================= fp16 mma.sync node GEMM (m16n8k16, hi/lo split) =================
#define A_STU 20   // u32 per A row (40 halves, 80 bytes)
#define W_STU 21   // u32 per W^T row (42 halves, 84 bytes)

template <int SPLIT, int PREACT, int DUAL, int OUTH>
__global__ __launch_bounds__(256, 2)
void gemm_fp16_kernel(const float* __restrict__ A, const float* __restrict__ W,
                      void* __restrict__ C, int M, int K, int Nc,
                      const float* __restrict__ bias, int act,
                      const float* __restrict__ abias,
                      const float* __restrict__ Wb, void* __restrict__ Cb) {
    extern __shared__ unsigned smg[];
    unsigned* Ahu = smg;
    unsigned* Alu = Ahu + 128 * A_STU;
    unsigned* Whu = Alu + (SPLIT ? 128 * A_STU : 0);
    unsigned* Wlu = Whu + 128 * W_STU;

    int tid = threadIdx.x;
    int warp = tid >> 5, lane = tid & 31;
    int qr = lane >> 2, qc = lane & 3;
    int m0 = blockIdx.y * 128;
    const float* Wp = W;
    void* Cp = C;
    int n0 = blockIdx.x * 128;
    if (DUAL) {
        if (blockIdx.x) { Wp = Wb; Cp = Cb; }
        n0 = 0;
    }
    int r0 = warp * 16;

    uint32_t Ah_s = smem_u32(Ahu);
    uint32_t Al_s = smem_u32(Alu);
    int laneRow = (lane & 7) + (lane & 8);
    int laneColB = ((lane >> 4) & 1) * 16;
    uint32_t lmH = Ah_s + (uint32_t)(r0 + laneRow) * 80 + (uint32_t)laneColB;
    uint32_t lmL = Al_s + (uint32_t)(r0 + laneRow) * 80 + (uint32_t)laneColB;

    int aRow[4], aCol[4];
#pragma unroll
    for (int i = 0; i < 4; i++) {
        int idx4 = tid + i * 256;
        aRow[i] = idx4 >> 3;
        aCol[i] = (idx4 & 7) << 2;
    }
    int wK2[2], wN[2];
#pragma unroll
    for (int i = 0; i < 2; i++) {
        int idx4 = tid + i * 256;
        wK2[i] = idx4 >> 5;
        wN[i] = (idx4 & 31) << 2;
    }

    float4 vA[4], vWa[2], vWb[2];
#define LOAD_TILE(KT)                                                           \
    {                                                                           \
        _Pragma("unroll")                                                       \
        for (int i = 0; i < 4; i++) {                                           \
            vA[i] = make_float4(0.f, 0.f, 0.f, 0.f);                            \
            if (m0 + aRow[i] < M)                                               \
                vA[i] = *(const float4*)(A + (size_t)(m0 + aRow[i]) * K + (KT) + aCol[i]); \
        }                                                                       \
        _Pragma("unroll")                                                       \
        for (int i = 0; i < 2; i++) {                                           \
            const float* wp0 = Wp + (size_t)((KT) + 2 * wK2[i]) * Nc + n0 + wN[i]; \
            vWa[i] = *(const float4*)wp0;                                       \
            vWb[i] = *(const float4*)(wp0 + Nc);                                \
        }                                                                       \
    }

    float acc[16][4];
#pragma unroll
    for (int n = 0; n < 16; n++)
#pragma unroll
        for (int j = 0; j < 4; j++) acc[n][j] = 0.f;

    LOAD_TILE(0);

    for (int kt = 0; kt < K; kt += 32) {
#pragma unroll
        for (int i = 0; i < 4; i++) {
            float4 v = vA[i];
            if (PREACT) {
                float4 ab = *(const float4*)(abias + kt + aCol[i]);
                v.x += ab.x; v.y += ab.y; v.z += ab.z; v.w += ab.w;
                v.x = v.x > 0.f ? v.x : expm1f(v.x);
                v.y = v.y > 0.f ? v.y : expm1f(v.y);
                v.z = v.z > 0.f ? v.z : expm1f(v.z);
                v.w = v.w > 0.f ? v.w : expm1f(v.w);
            }
            __half h0 = __float2half_rn(v.x), h1 = __float2half_rn(v.y);
            __half h2_ = __float2half_rn(v.z), h3 = __float2half_rn(v.w);
            int base = aRow[i] * A_STU + (aCol[i] >> 1);
            Ahu[base] = h2_bits(__halves2half2(h0, h1));
            Ahu[base + 1] = h2_bits(__halves2half2(h2_, h3));
            if (SPLIT) {
                __half l0 = __float2half_rn(v.x - __half2float(h0));
                __half l1 = __float2half_rn(v.y - __half2float(h1));
                __half l2 = __float2half_rn(v.z - __half2float(h2_));
                __half l3 = __float2half_rn(v.w - __half2float(h3));
                Alu[base] = h2_bits(__halves2half2(l0, l1));
                Alu[base + 1] = h2_bits(__halves2half2(l2, l3));
            }
        }
#pragma unroll
        for (int i = 0; i < 2; i++) {
            float fa[4] = {vWa[i].x, vWa[i].y, vWa[i].z, vWa[i].w};
            float fb[4] = {vWb[i].x, vWb[i].y, vWb[i].z, vWb[i].w};
#pragma unroll
            for (int j = 0; j < 4; j++) {
                __half ha = __float2half_rn(fa[j]), hb = __float2half_rn(fb[j]);
                Whu[(wN[i] + j) * W_STU + wK2[i]] = h2_bits(__halves2half2(ha, hb));
                if (SPLIT) {
                    __half la = __float2half_rn(fa[j] - __half2float(ha));
                    __half lb = __float2half_rn(fb[j] - __half2float(hb));
                    Wlu[(wN[i] + j) * W_STU + wK2[i]] = h2_bits(__halves2half2(la, lb));
                }
            }
        }
        __syncthreads();

        if (kt + 32 < K) LOAD_TILE(kt + 32);

#pragma unroll
        for (int kk = 0; kk < 2; kk++) {
            unsigned ah0, ah1, ah2, ah3, al0, al1, al2, al3;
            asm volatile(
                "ldmatrix.sync.aligned.m8n8.x4.shared.b16 {%0,%1,%2,%3}, [%4];"
                : "=r"(ah0), "=r"(ah1), "=r"(ah2), "=r"(ah3)
                : "r"(lmH + (uint32_t)kk * 32));
            if (SPLIT) {
                asm volatile(
                    "ldmatrix.sync.aligned.m8n8.x4.shared.b16 {%0,%1,%2,%3}, [%4];"
                    : "=r"(al0), "=r"(al1), "=r"(al2), "=r"(al3)
                    : "r"(lmL + (uint32_t)kk * 32));
            }
#pragma unroll
            for (int nc = 0; nc < 16; nc++) {
                int widx = (nc * 8 + qr) * W_STU + kk * 8 + qc;
                unsigned bh0 = Whu[widx];
                unsigned bh1 = Whu[widx + 4];
                asm volatile(
                    "mma.sync.aligned.m16n8k16.row.col.f32.f16.f16.f32 "
                    "{%0,%1,%2,%3}, {%4,%5,%6,%7}, {%8,%9}, {%0,%1,%2,%3};"
                    : "+f"(acc[nc][0]), "+f"(acc[nc][1]), "+f"(acc[nc][2]), "+f"(acc[nc][3])
                    : "r"(ah0), "r"(ah1), "r"(ah2), "r"(ah3), "r"(bh0), "r"(bh1));
                if (SPLIT) {
                    unsigned bl0 = Wlu[widx];
                    unsigned bl1 = Wlu[widx + 4];
                    asm volatile(
                        "mma.sync.aligned.m16n8k16.row.col.f32.f16.f16.f32 "
                        "{%0,%1,%2,%3}, {%4,%5,%6,%7}, {%8,%9}, {%0,%1,%2,%3};"
                        : "+f"(acc[nc][0]), "+f"(acc[nc][1]), "+f"(acc[nc][2]), "+f"(acc[nc][3])
                        : "r"(ah0), "r"(ah1), "r"(ah2), "r"(ah3), "r"(bl0), "r"(bl1));
                    asm volatile(
                        "mma.sync.aligned.m16n8k16.row.col.f32.f16.f16.f32 "
                        "{%0,%1,%2,%3}, {%4,%5,%6,%7}, {%8,%9}, {%0,%1,%2,%3};"
                        : "+f"(acc[nc][0]), "+f"(acc[nc][1]), "+f"(acc[nc][2]), "+f"(acc[nc][3])
                        : "r"(al0), "r"(al1), "r"(al2), "r"(al3), "r"(bh0), "r"(bh1));
                }
            }
        }
        __syncthreads();
    }
#undef LOAD_TILE

    int row0 = m0 + r0 + qr;
    int row1 = row0 + 8;
#pragma unroll
    for (int nc = 0; nc < 16; nc++) {
        int c0 = n0 + nc * 8 + qc * 2;
        float bz0 = 0.f, bz1 = 0.f;
        if (bias) { bz0 = __ldg(bias + c0); bz1 = __ldg(bias + c0 + 1); }
        float u0 = acc[nc][0] + bz0, u1 = acc[nc][1] + bz1;
        float u2 = acc[nc][2] + bz0, u3 = acc[nc][3] + bz1;
        if (act) {
            u0 = u0 > 0.f ? u0 : expm1f(u0);
            u1 = u1 > 0.f ? u1 : expm1f(u1);
            u2 = u2 > 0.f ? u2 : expm1f(u2);
            u3 = u3 > 0.f ? u3 : expm1f(u3);
        }
        if (OUTH) {
            if (row0 < M) *(__half2*)((__half*)Cp + (size_t)row0 * Nc + c0) = __floats2half2_rn(u0, u1);
            if (row1 < M) *(__half2*)((__half*)Cp + (size_t)row1 * Nc + c0) = __floats2half2_rn(u2, u3);
        } else {
            if (row0 < M) *(float2*)((float*)Cp + (size_t)row0 * Nc + c0) = make_float2(u0, u1);
            if (row1 < M) *(float2*)((float*)Cp + (size_t)row1 * Nc + c0) = make_float2(u2, u3);
        }
    }
}

// ============================================================================
// Persistent fp16 edge decoder (mma.sync m16n8k16.f16, ldmatrix A-fragments,
// half2 phase-1, per-warp epilogue slices, next-tile index prefetch)
// ============================================================================
#define TS_HW 68   // u32 words per t row (136 halves; row stride 272 bytes)

__global__ __launch_bounds__(256, 3)
void decoder_fp16_kernel(const __half* __restrict__ Ad, const __half* __restrict__ Bd,
                         const int* __restrict__ ei,
                         const float* __restrict__ b1, const float* __restrict__ W2,
                         const float* __restrict__ b2, const float* __restrict__ W3,
                         const float* __restrict__ b3, float* __restrict__ out,
                         int E, int numTiles) {
    extern __shared__ unsigned smemd[];
    unsigned* tS = smemd;
    unsigned* b1h = smemd + 128 * TS_HW;
    float* esum = (float*)(b1h + 64);
    int tid = threadIdx.x;
    int warp = tid >> 5, lane = tid & 31;
    int qr = lane >> 2, qc = lane & 3;
    int nBase = warp * 16;
    uint32_t tS_s = smem_u32(tS);
    int laneRow = (lane & 7) + (lane & 8);
    int laneColB = ((lane >> 4) & 1) * 16;
    uint32_t lmBase = tS_s + (uint32_t)laneRow * 272 + (uint32_t)laneColB;
    float* esumW = esum + warp * 128;

    unsigned bf[8][2][2];
#pragma unroll
    for (int c = 0; c < 8; c++) {
        int kb = c * 16;
#pragma unroll
        for (int ncl = 0; ncl < 2; ncl++) {
            int n = nBase + ncl * 8 + qr;
            bf[c][ncl][0] = h2_bits(__floats2half2_rn(
                __ldg(W2 + (kb + 2 * qc) * 128 + n), __ldg(W2 + (kb + 2 * qc + 1) * 128 + n)));
            bf[c][ncl][1] = h2_bits(__floats2half2_rn(
                __ldg(W2 + (kb + 2 * qc + 8) * 128 + n), __ldg(W2 + (kb + 2 * qc + 9) * 128 + n)));
        }
    }
    float bb0[2], bb1[2], w30[2], w31[2];
#pragma unroll
    for (int ncl = 0; ncl < 2; ncl++) {
        int c0 = nBase + ncl * 8 + qc * 2;
        bb0[ncl] = __ldg(b2 + c0); bb1[ncl] = __ldg(b2 + c0 + 1);
        w30[ncl] = __ldg(W3 + c0); w31[ncl] = __ldg(W3 + c0 + 1);
    }
    float b3v = __ldg(b3);
    if (tid < 64) b1h[tid] = h2_bits(__floats2half2_rn(__ldg(b1 + 2 * tid), __ldg(b1 + 2 * tid + 1)));
    __syncthreads();

    const __half2 hz = __floats2half2_rn(0.f, 0.f);
    int eloc = tid >> 1;
    int half_ = tid & 1;

    int sCur = 0, dCur = 0, vCur = 0;
    {
        int tile0 = blockIdx.x;
        if (tile0 < numTiles) {
            int e = tile0 * 128 + eloc;
            if (e < E) { sCur = ei[e]; dCur = ei[E + e]; vCur = 1; }
        }
    }

    for (int tile = blockIdx.x; tile < numTiles; tile += gridDim.x) {
        __syncthreads();

        {
            uint4* trow4 = (uint4*)(tS + eloc * TS_HW + half_ * 32);
            if (vCur) {
                const uint4* ap = (const uint4*)(Ad + (size_t)sCur * 128) + half_ * 8;
                const uint4* bp = (const uint4*)(Bd + (size_t)dCur * 128) + half_ * 8;
                const uint4* cb = (const uint4*)b1h + half_ * 8;
#pragma unroll
                for (int j = 0; j < 8; j++) {
                    uint4 av = __ldg(ap + j);
                    uint4 bv = __ldg(bp + j);
                    uint4 cv = cb[j];
                    uint4 r;
                    r.x = h2_bits(__hmax2(__hadd2(__hadd2(bits_h2(av.x), bits_h2(bv.x)), bits_h2(cv.x)), hz));
                    r.y = h2_bits(__hmax2(__hadd2(__hadd2(bits_h2(av.y), bits_h2(bv.y)), bits_h2(cv.y)), hz));
                    r.z = h2_bits(__hmax2(__hadd2(__hadd2(bits_h2(av.z), bits_h2(bv.z)), bits_h2(cv.z)), hz));
                    r.w = h2_bits(__hmax2(__hadd2(__hadd2(bits_h2(av.w), bits_h2(bv.w)), bits_h2(cv.w)), hz));
                    trow4[j] = r;
                }
            } else {
                uint4 z4 = make_uint4(0u, 0u, 0u, 0u);
#pragma unroll
                for (int j = 0; j < 8; j++) trow4[j] = z4;
            }
        }
        __syncthreads();

        {
            int tNext = tile + gridDim.x;
            vCur = 0;
            if (tNext < numTiles) {
                int e = tNext * 128 + eloc;
                if (e < E) { sCur = ei[e]; dCur = ei[E + e]; vCur = 1; }
            }
        }

#pragma unroll 1
        for (int m = 0; m < 8; m++) {
            int r0 = m * 16;
            uint32_t rowAddr = lmBase + (uint32_t)r0 * 272;
            float acc[2][4];
            acc[0][0] = acc[0][1] = acc[0][2] = acc[0][3] = 0.f;
            acc[1][0] = acc[1][1] = acc[1][2] = acc[1][3] = 0.f;
#pragma unroll
            for (int c = 0; c < 8; c++) {
                unsigned a0, a1, a2, a3;
                asm volatile(
                    "ldmatrix.sync.aligned.m8n8.x4.shared.b16 {%0,%1,%2,%3}, [%4];"
                    : "=r"(a0), "=r"(a1), "=r"(a2), "=r"(a3)
                    : "r"(rowAddr + (uint32_t)c * 32));
                asm volatile(
                    "mma.sync.aligned.m16n8k16.row.col.f32.f16.f16.f32 "
                    "{%0,%1,%2,%3}, {%4,%5,%6,%7}, {%8,%9}, {%0,%1,%2,%3};"
                    : "+f"(acc[0][0]), "+f"(acc[0][1]), "+f"(acc[0][2]), "+f"(acc[0][3])
                    : "r"(a0), "r"(a1), "r"(a2), "r"(a3), "r"(bf[c][0][0]), "r"(bf[c][0][1]));
                asm volatile(
                    "mma.sync.aligned.m16n8k16.row.col.f32.f16.f16.f32 "
                    "{%0,%1,%2,%3}, {%4,%5,%6,%7}, {%8,%9}, {%0,%1,%2,%3};"
                    : "+f"(acc[1][0]), "+f"(acc[1][1]), "+f"(acc[1][2]), "+f"(acc[1][3])
                    : "r"(a0), "r"(a1), "r"(a2), "r"(a3), "r"(bf[c][1][0]), "r"(bf[c][1][1]));
            }
            float e0 = 0.f, e1 = 0.f;
#pragma unroll
            for (int ncl = 0; ncl < 2; ncl++) {
                e0 += fmaxf(acc[ncl][0] + bb0[ncl], 0.f) * w30[ncl]
                    + fmaxf(acc[ncl][1] + bb1[ncl], 0.f) * w31[ncl];
                e1 += fmaxf(acc[ncl][2] + bb0[ncl], 0.f) * w30[ncl]
                    + fmaxf(acc[ncl][3] + bb1[ncl], 0.f) * w31[ncl];
            }
            e0 += __shfl_xor_sync(0xffffffffu, e0, 1);
            e0 += __shfl_xor_sync(0xffffffffu, e0, 2);
            e1 += __shfl_xor_sync(0xffffffffu, e1, 1);
            e1 += __shfl_xor_sync(0xffffffffu, e1, 2);
            if (qc == 0) {
                esumW[r0 + qr] = e0;
                esumW[r0 + qr + 8] = e1;
            }
        }
        __syncthreads();

        if (tid < 128) {
            int e = tile * 128 + tid;
            if (e < E) {
                float s = esum[tid];
#pragma unroll
                for (int w = 1; w < 8; w++) s += esum[w * 128 + tid];
                out[e] = s + b3v;
            }
        }
    }
}

extern "C" void kernel_launch(void* const* d_in, const int* in_sizes, int n_in,
                              void* d_out, int out_size) {
    const int* node_ids = (const int*)d_in[0];
    const int* ei       = (const int*)d_in[1];
    const int* nei      = (const int*)d_in[2];
    const float* eattr  = (const float*)d_in[3];
    const float* emb    = (const float*)d_in[4];
    const float* W_in   = (const float*)d_in[5];
    const float* b_in   = (const float*)d_in[6];
    const float* W_out  = (const float*)d_in[7];
    const float* b_out  = (const float*)d_in[8];
    const float* W1     = (const float*)d_in[9];
    const float* b1     = (const float*)d_in[10];
    const float* W2     = (const float*)d_in[11];
    const float* b2     = (const float*)d_in[12];
    const float* W3     = (const float*)d_in[13];
    const float* b3     = (const float*)d_in[14];
    int N = in_sizes[0];
    int E = in_sizes[3];
    float* out = (float*)d_out;

    float *agg1, *x1, *x2;
    __half *embh, *h2h, *Ad, *Bd;
    int *off1, *off2;
    int2 *pair1, *pair2;
    cudaGetSymbolAddress((void**)&embh, g_embh);
    cudaGetSymbolAddress((void**)&agg1, g_agg1);
    cudaGetSymbolAddress((void**)&x1, g_x1);
    cudaGetSymbolAddress((void**)&h2h, g_h2h);
    cudaGetSymbolAddress((void**)&x2, g_x2);
    cudaGetSymbolAddress((void**)&Ad, g_Adec);
    cudaGetSymbolAddress((void**)&Bd, g_Bdec);
    cudaGetSymbolAddress((void**)&off1, g_off1);
    cudaGetSymbolAddress((void**)&off2, g_off2);
    cudaGetSymbolAddress((void**)&pair1, g_pair1);
    cudaGetSymbolAddress((void**)&pair2, g_pair2);

    const int T = 256;
    init_f2h_kernel<<<(N * 32 + T - 1) / T, T>>>(emb, embh, N, N * 32);
    deg_cnt_kernel<<<(E + T - 1) / T, T>>>(ei, eattr, nei, E);
    scan2_kernel<<<1, 1024>>>(N, E);
    fill_kernel<<<(E + T - 1) / T, T>>>(ei, nei, eattr, node_ids, E);

    int mBlocks = (N + 127) / 128;
    int smem_split = (128 * A_STU * 2 + 128 * W_STU * 2) * 4;
    cudaFuncSetAttribute((const void*)gemm_fp16_kernel<1, 0, 0, 0>,
                         cudaFuncAttributeMaxDynamicSharedMemorySize, smem_split);
    cudaFuncSetAttribute((const void*)gemm_fp16_kernel<1, 0, 0, 1>,
                         cudaFuncAttributeMaxDynamicSharedMemorySize, smem_split);
    cudaFuncSetAttribute((const void*)gemm_fp16_kernel<1, 1, 1, 1>,
                         cudaFuncAttributeMaxDynamicSharedMemorySize, smem_split);

    int gatherBlocks = (N * 16 + T - 1) / T;

    // conv1: fp16 gather-aggregate emb, then fp16-split GEMM with fused bias+elu
    gather_f16_kernel<<<gatherBlocks, T>>>(embh, agg1, off1, pair1, N);
    gemm_fp16_kernel<1, 0, 0, 0><<<dim3(2, mBlocks), 256, smem_split>>>(
        agg1, W_in, x1, N, 128, 256, b_in, 1, nullptr, nullptr, nullptr);

    // conv2: fp16-split GEMM (fp16 out) then fp16 gather-aggregate
    gemm_fp16_kernel<1, 0, 0, 1><<<dim3(1, mBlocks), 256, smem_split>>>(
        x1, W_out, h2h, N, 256, 128, nullptr, 0, nullptr, nullptr, nullptr);
    gather_f16_kernel<<<gatherBlocks, T>>>(h2h, x2, off2, pair2, N);

    // merged dual pre-GEMMs (fp16 split; elu(x2+b_out) fused on A, fp16 outputs)
    gemm_fp16_kernel<1, 1, 1, 1><<<dim3(2, mBlocks), 256, smem_split>>>(
        x2, W1, Ad, N, 128, 128, nullptr, 0, b_out, W1 + 128 * 128, Bd);

    // persistent fp16 tensor-core edge decoder
    int numTiles = (E + 127) / 128;
    int smem_dec = (128 * TS_HW + 64 + 8 * 128) * 4;
    cudaFuncSetAttribute(decoder_fp16_kernel, cudaFuncAttributeMaxDynamicSharedMemorySize, smem_dec);
    int grid_dec = 3 * 148;
    if (grid_dec > numTiles) grid_dec = numTiles;
    decoder_fp16_kernel<<<grid_dec, 256, smem_dec>>>(Ad, Bd, ei, b1, W2, b2, W3, b3, out, E, numTiles);
}

// round 17
// speedup vs baseline: 1.0112x; 1.0024x over previous
#include <cuda_runtime.h>
#include <cuda_fp16.h>
#include <math.h>
#include <stdint.h>

#define MAXN 50000
#define MAXE 800000

// ---- scratch (device globals; no allocation allowed) ----
__device__ float g_deg1[MAXN];
__device__ int   g_cnt1[MAXN];
__device__ int   g_deg2[MAXN];
__device__ int   g_off1[MAXN + 1];
__device__ int   g_off2[MAXN + 1];
__device__ int   g_rank1[MAXE];
__device__ int   g_rank2[MAXE];
__device__ int2  g_pair1[MAXE];
__device__ int2  g_pair2[MAXE];
__device__ __half g_embh[(size_t)MAXN * 128];
__device__ float g_agg1[(size_t)MAXN * 128];
__device__ float g_x1[(size_t)MAXN * 256];
__device__ __half g_h2h[(size_t)MAXN * 128];
__device__ float g_x2[(size_t)MAXN * 128];
__device__ __half g_Adec[(size_t)MAXN * 128];
__device__ __half g_Bdec[(size_t)MAXN * 128];

__device__ __forceinline__ unsigned h2_bits(__half2 h) {
    unsigned u;
    *(__half2*)&u = h;
    return u;
}
__device__ __forceinline__ __half2 bits_h2(unsigned u) {
    return *(__half2*)&u;
}
__device__ __forceinline__ uint32_t smem_u32(const void* p) {
    uint32_t a;
    asm("{ .reg .u64 t; cvta.to.shared.u64 t, %1; cvt.u32.u64 %0, t; }" : "=r"(a) : "l"(p));
    return a;
}

// ================= fused zero-init + emb fp16 conversion =================
__global__ void init_f2h_kernel(const float* __restrict__ emb, __half* __restrict__ embh,
                                int N, int n4) {
    int i = blockIdx.x * blockDim.x + threadIdx.x;
    if (i < N) {
        g_deg1[i] = 0.f; g_cnt1[i] = 0; g_deg2[i] = 0;
    }
    for (int j = i; j < n4; j += gridDim.x * blockDim.x) {
        float4 v = ((const float4*)emb)[j];
        uint2 o;
        o.x = h2_bits(__floats2half2_rn(v.x, v.y));
        o.y = h2_bits(__floats2half2_rn(v.z, v.w));
        ((uint2*)embh)[j] = o;
    }
}

// ================= CSR build =================
__global__ void deg_cnt_kernel(const int* __restrict__ ei, const float* __restrict__ w,
                               const int* __restrict__ nei, int E) {
    int e = blockIdx.x * blockDim.x + threadIdx.x;
    if (e < E) {
        int c1 = ei[E + e];
        atomicAdd(&g_deg1[c1], w[e]);
        g_rank1[e] = atomicAdd(&g_cnt1[c1], 1);
        g_rank2[e] = atomicAdd(&g_deg2[nei[E + e]], 1);
    }
}

__global__ __launch_bounds__(1024, 1)
void scan2_kernel(int N, int E) {
    __shared__ int warpTot[32];
    int tid = threadIdx.x;
    int lane = tid & 31, w = tid >> 5;
    int chunk = (N + 1023) / 1024;
    int beg = tid * chunk;
    int end = beg + chunk; if (end > N) end = N;
#pragma unroll 1
    for (int a = 0; a < 2; a++) {
        const int* c = a ? g_deg2 : g_cnt1;
        int* o = a ? g_off2 : g_off1;
        __syncthreads();
        int t = 0;
        for (int i = beg; i < end; i++) t += c[i];
        int v = t;
#pragma unroll
        for (int d = 1; d < 32; d <<= 1) {
            int u = __shfl_up_sync(0xffffffffu, v, d);
            if (lane >= d) v += u;
        }
        if (lane == 31) warpTot[w] = v;
        __syncthreads();
        if (w == 0) {
            int x = warpTot[lane];
#pragma unroll
            for (int d = 1; d < 32; d <<= 1) {
                int u = __shfl_up_sync(0xffffffffu, x, d);
                if (lane >= d) x += u;
            }
            warpTot[lane] = x;
        }
        __syncthreads();
        int run = v - t + (w > 0 ? warpTot[w - 1] : 0);
        for (int i = beg; i < end; i++) { o[i] = run; run += c[i]; }
    }
    if (tid == 0) { g_off1[N] = E; g_off2[N] = E; }
}

__global__ void fill_kernel(const int* __restrict__ ei, const int* __restrict__ nei,
                            const float* __restrict__ w, const int* __restrict__ node_ids,
                            int E) {
    int e = blockIdx.x * blockDim.x + threadIdx.x;
    if (e >= E) return;
    {
        int r = ei[e], c = ei[E + e];
        float dr = g_deg1[r], dc = g_deg1[c];
        float nrm = (dr > 0.f ? rsqrtf(dr) : 0.f) * w[e] * (dc > 0.f ? rsqrtf(dc) : 0.f);
        g_pair1[g_off1[c] + g_rank1[e]] = make_int2(node_ids[r], __float_as_int(nrm));
    }
    {
        int r = nei[e], c = nei[E + e];
        float dr = (float)g_deg2[r], dc = (float)g_deg2[c];
        float nrm = (dr > 0.f ? rsqrtf(dr) : 0.f) * (dc > 0.f ? rsqrtf(dc) : 0.f);
        g_pair2[g_off2[c] + g_rank2[e]] = make_int2(r, __float_as_int(nrm));
    }
}

// ---- gather-reduce from fp16 rows: half-warp per node, uint4 lane loads ----
__global__ void gather_f16_kernel(const __half* __restrict__ h, float* __restrict__ out,
                                  const int* __restrict__ off, const int2* __restrict__ pair,
                                  int N) {
    int gw = (blockIdx.x * blockDim.x + threadIdx.x) >> 4;
    if (gw >= N) return;
    int lane = threadIdx.x & 15;
    int s = off[gw], t = off[gw + 1];
    float acc0[8] = {0.f, 0.f, 0.f, 0.f, 0.f, 0.f, 0.f, 0.f};
    float acc1[8] = {0.f, 0.f, 0.f, 0.f, 0.f, 0.f, 0.f, 0.f};
    int i = s;
#define GF16_STEP(P, W, ACC)                                                   \
    {                                                                          \
        float nn = __int_as_float((P).y);                                      \
        float2 v0 = __half22float2(bits_h2((W).x));                            \
        float2 v1 = __half22float2(bits_h2((W).y));                            \
        float2 v2 = __half22float2(bits_h2((W).z));                            \
        float2 v3 = __half22float2(bits_h2((W).w));                            \
        ACC[0] = fmaf(v0.x, nn, ACC[0]); ACC[1] = fmaf(v0.y, nn, ACC[1]);      \
        ACC[2] = fmaf(v1.x, nn, ACC[2]); ACC[3] = fmaf(v1.y, nn, ACC[3]);      \
        ACC[4] = fmaf(v2.x, nn, ACC[4]); ACC[5] = fmaf(v2.y, nn, ACC[5]);      \
        ACC[6] = fmaf(v3.x, nn, ACC[6]); ACC[7] = fmaf(v3.y, nn, ACC[7]);      \
    }
    for (; i + 4 <= t; i += 4) {
        int2 p0 = __ldg(pair + i), p1 = __ldg(pair + i + 1);
        int2 p2 = __ldg(pair + i + 2), p3 = __ldg(pair + i + 3);
        uint4 w0 = *(const uint4*)(h + (size_t)p0.x * 128 + lane * 8);
        uint4 w1 = *(const uint4*)(h + (size_t)p1.x * 128 + lane * 8);
        uint4 w2 = *(const uint4*)(h + (size_t)p2.x * 128 + lane * 8);
        uint4 w3 = *(const uint4*)(h + (size_t)p3.x * 128 + lane * 8);
        GF16_STEP(p0, w0, acc0) GF16_STEP(p1, w1, acc1)
        GF16_STEP(p2, w2, acc0) GF16_STEP(p3, w3, acc1)
    }
    for (; i + 2 <= t; i += 2) {
        int2 p0 = __ldg(pair + i), p1 = __ldg(pair + i + 1);
        uint4 w0 = *(const uint4*)(h + (size_t)p0.x * 128 + lane * 8);
        uint4 w1 = *(const uint4*)(h + (size_t)p1.x * 128 + lane * 8);
        GF16_STEP(p0, w0, acc0) GF16_STEP(p1, w1, acc1)
    }
    if (i < t) {
        int2 p0 = __ldg(pair + i);
        uint4 w0 = *(const uint4*)(h + (size_t)p0.x * 128 + lane * 8);
        GF16_STEP(p0, w0, acc0)
    }
#undef GF16_STEP
    float* o = out + (size_t)gw * 128 + lane * 8;
    *(float4*)o = make_float4(acc0[0] + acc1[0], acc0[1] + acc1[1],
                              acc0[2] + acc1[2], acc0[3] + acc1[3]);
    *(float4*)(o + 4) = make_float4(acc0[4] + acc1[4], acc0[5] + acc1[5],
                                    acc0[6] + acc1[6], acc0[7] + acc1[7]);
}

// ================= fp16 mma.sync node GEMM (m16n8k16, hi/lo split) =================
#define A_STU 20
#define W_STU 21

template <int SPLIT, int PREACT, int DUAL, int OUTH>
__global__ __launch_bounds__(256, 2)
void gemm_fp16_kernel(const float* __restrict__ A, const float* __restrict__ W,
                      void* __restrict__ C, int M, int K, int Nc,
                      const float* __restrict__ bias, int act,
                      const float* __restrict__ abias,
                      const float* __restrict__ Wb, void* __restrict__ Cb) {
    extern __shared__ unsigned smg[];
    unsigned* Ahu = smg;
    unsigned* Alu = Ahu + 128 * A_STU;
    unsigned* Whu = Alu + (SPLIT ? 128 * A_STU : 0);
    unsigned* Wlu = Whu + 128 * W_STU;

    int tid = threadIdx.x;
    int warp = tid >> 5, lane = tid & 31;
    int qr = lane >> 2, qc = lane & 3;
    int m0 = blockIdx.y * 128;
    const float* Wp = W;
    void* Cp = C;
    int n0 = blockIdx.x * 128;
    if (DUAL) {
        if (blockIdx.x) { Wp = Wb; Cp = Cb; }
        n0 = 0;
    }
    int r0 = warp * 16;

    uint32_t Ah_s = smem_u32(Ahu);
    uint32_t Al_s = smem_u32(Alu);
    int laneRow = (lane & 7) + (lane & 8);
    int laneColB = ((lane >> 4) & 1) * 16;
    uint32_t lmH = Ah_s + (uint32_t)(r0 + laneRow) * 80 + (uint32_t)laneColB;
    uint32_t lmL = Al_s + (uint32_t)(r0 + laneRow) * 80 + (uint32_t)laneColB;

    int aRow[4], aCol[4];
#pragma unroll
    for (int i = 0; i < 4; i++) {
        int idx4 = tid + i * 256;
        aRow[i] = idx4 >> 3;
        aCol[i] = (idx4 & 7) << 2;
    }
    int wK2[2], wN[2];
#pragma unroll
    for (int i = 0; i < 2; i++) {
        int idx4 = tid + i * 256;
        wK2[i] = idx4 >> 5;
        wN[i] = (idx4 & 31) << 2;
    }

    float4 vA[4], vWa[2], vWb[2];
#define LOAD_TILE(KT)                                                           \
    {                                                                           \
        _Pragma("unroll")                                                       \
        for (int i = 0; i < 4; i++) {                                           \
            vA[i] = make_float4(0.f, 0.f, 0.f, 0.f);                            \
            if (m0 + aRow[i] < M)                                               \
                vA[i] = *(const float4*)(A + (size_t)(m0 + aRow[i]) * K + (KT) + aCol[i]); \
        }                                                                       \
        _Pragma("unroll")                                                       \
        for (int i = 0; i < 2; i++) {                                           \
            const float* wp0 = Wp + (size_t)((KT) + 2 * wK2[i]) * Nc + n0 + wN[i]; \
            vWa[i] = *(const float4*)wp0;                                       \
            vWb[i] = *(const float4*)(wp0 + Nc);                                \
        }                                                                       \
    }

    float acc[16][4];
#pragma unroll
    for (int n = 0; n < 16; n++)
#pragma unroll
        for (int j = 0; j < 4; j++) acc[n][j] = 0.f;

    LOAD_TILE(0);

    for (int kt = 0; kt < K; kt += 32) {
#pragma unroll
        for (int i = 0; i < 4; i++) {
            float4 v = vA[i];
            if (PREACT) {
                float4 ab = *(const float4*)(abias + kt + aCol[i]);
                v.x += ab.x; v.y += ab.y; v.z += ab.z; v.w += ab.w;
                v.x = v.x > 0.f ? v.x : expm1f(v.x);
                v.y = v.y > 0.f ? v.y : expm1f(v.y);
                v.z = v.z > 0.f ? v.z : expm1f(v.z);
                v.w = v.w > 0.f ? v.w : expm1f(v.w);
            }
            __half h0 = __float2half_rn(v.x), h1 = __float2half_rn(v.y);
            __half h2_ = __float2half_rn(v.z), h3 = __float2half_rn(v.w);
            int base = aRow[i] * A_STU + (aCol[i] >> 1);
            Ahu[base] = h2_bits(__halves2half2(h0, h1));
            Ahu[base + 1] = h2_bits(__halves2half2(h2_, h3));
            if (SPLIT) {
                __half l0 = __float2half_rn(v.x - __half2float(h0));
                __half l1 = __float2half_rn(v.y - __half2float(h1));
                __half l2 = __float2half_rn(v.z - __half2float(h2_));
                __half l3 = __float2half_rn(v.w - __half2float(h3));
                Alu[base] = h2_bits(__halves2half2(l0, l1));
                Alu[base + 1] = h2_bits(__halves2half2(l2, l3));
            }
        }
#pragma unroll
        for (int i = 0; i < 2; i++) {
            float fa[4] = {vWa[i].x, vWa[i].y, vWa[i].z, vWa[i].w};
            float fb[4] = {vWb[i].x, vWb[i].y, vWb[i].z, vWb[i].w};
#pragma unroll
            for (int j = 0; j < 4; j++) {
                __half ha = __float2half_rn(fa[j]), hb = __float2half_rn(fb[j]);
                Whu[(wN[i] + j) * W_STU + wK2[i]] = h2_bits(__halves2half2(ha, hb));
                if (SPLIT) {
                    __half la = __float2half_rn(fa[j] - __half2float(ha));
                    __half lb = __float2half_rn(fb[j] - __half2float(hb));
                    Wlu[(wN[i] + j) * W_STU + wK2[i]] = h2_bits(__halves2half2(la, lb));
                }
            }
        }
        __syncthreads();

        if (kt + 32 < K) LOAD_TILE(kt + 32);

#pragma unroll
        for (int kk = 0; kk < 2; kk++) {
            unsigned ah0, ah1, ah2, ah3, al0, al1, al2, al3;
            asm volatile(
                "ldmatrix.sync.aligned.m8n8.x4.shared.b16 {%0,%1,%2,%3}, [%4];"
                : "=r"(ah0), "=r"(ah1), "=r"(ah2), "=r"(ah3)
                : "r"(lmH + (uint32_t)kk * 32));
            if (SPLIT) {
                asm volatile(
                    "ldmatrix.sync.aligned.m8n8.x4.shared.b16 {%0,%1,%2,%3}, [%4];"
                    : "=r"(al0), "=r"(al1), "=r"(al2), "=r"(al3)
                    : "r"(lmL + (uint32_t)kk * 32));
            }
#pragma unroll
            for (int nc = 0; nc < 16; nc++) {
                int widx = (nc * 8 + qr) * W_STU + kk * 8 + qc;
                unsigned bh0 = Whu[widx];
                unsigned bh1 = Whu[widx + 4];
                asm volatile(
                    "mma.sync.aligned.m16n8k16.row.col.f32.f16.f16.f32 "
                    "{%0,%1,%2,%3}, {%4,%5,%6,%7}, {%8,%9}, {%0,%1,%2,%3};"
                    : "+f"(acc[nc][0]), "+f"(acc[nc][1]), "+f"(acc[nc][2]), "+f"(acc[nc][3])
                    : "r"(ah0), "r"(ah1), "r"(ah2), "r"(ah3), "r"(bh0), "r"(bh1));
                if (SPLIT) {
                    unsigned bl0 = Wlu[widx];
                    unsigned bl1 = Wlu[widx + 4];
                    asm volatile(
                        "mma.sync.aligned.m16n8k16.row.col.f32.f16.f16.f32 "
                        "{%0,%1,%2,%3}, {%4,%5,%6,%7}, {%8,%9}, {%0,%1,%2,%3};"
                        : "+f"(acc[nc][0]), "+f"(acc[nc][1]), "+f"(acc[nc][2]), "+f"(acc[nc][3])
                        : "r"(ah0), "r"(ah1), "r"(ah2), "r"(ah3), "r"(bl0), "r"(bl1));
                    asm volatile(
                        "mma.sync.aligned.m16n8k16.row.col.f32.f16.f16.f32 "
                        "{%0,%1,%2,%3}, {%4,%5,%6,%7}, {%8,%9}, {%0,%1,%2,%3};"
                        : "+f"(acc[nc][0]), "+f"(acc[nc][1]), "+f"(acc[nc][2]), "+f"(acc[nc][3])
                        : "r"(al0), "r"(al1), "r"(al2), "r"(al3), "r"(bh0), "r"(bh1));
                }
            }
        }
        __syncthreads();
    }
#undef LOAD_TILE

    int row0 = m0 + r0 + qr;
    int row1 = row0 + 8;
#pragma unroll
    for (int nc = 0; nc < 16; nc++) {
        int c0 = n0 + nc * 8 + qc * 2;
        float bz0 = 0.f, bz1 = 0.f;
        if (bias) { bz0 = __ldg(bias + c0); bz1 = __ldg(bias + c0 + 1); }
        float u0 = acc[nc][0] + bz0, u1 = acc[nc][1] + bz1;
        float u2 = acc[nc][2] + bz0, u3 = acc[nc][3] + bz1;
        if (act) {
            u0 = u0 > 0.f ? u0 : expm1f(u0);
            u1 = u1 > 0.f ? u1 : expm1f(u1);
            u2 = u2 > 0.f ? u2 : expm1f(u2);
            u3 = u3 > 0.f ? u3 : expm1f(u3);
        }
        if (OUTH) {
            if (row0 < M) *(__half2*)((__half*)Cp + (size_t)row0 * Nc + c0) = __floats2half2_rn(u0, u1);
            if (row1 < M) *(__half2*)((__half*)Cp + (size_t)row1 * Nc + c0) = __floats2half2_rn(u2, u3);
        } else {
            if (row0 < M) *(float2*)((float*)Cp + (size_t)row0 * Nc + c0) = make_float2(u0, u1);
            if (row1 < M) *(float2*)((float*)Cp + (size_t)row1 * Nc + c0) = make_float2(u2, u3);
        }
    }
}

// ============================================================================
// Persistent fp16 edge decoder — 4 CTAs/SM, 2 barriers/tile
// ============================================================================
#define TS_HW 68

__global__ __launch_bounds__(256, 4)
void decoder_fp16_kernel(const __half* __restrict__ Ad, const __half* __restrict__ Bd,
                         const int* __restrict__ ei,
                         const float* __restrict__ b1, const float* __restrict__ W2,
                         const float* __restrict__ b2, const float* __restrict__ W3,
                         const float* __restrict__ b3, float* __restrict__ out,
                         int E, int numTiles) {
    extern __shared__ unsigned smemd[];
    unsigned* tS = smemd;
    unsigned* b1h = smemd + 128 * TS_HW;
    float* esum = (float*)(b1h + 64);
    int tid = threadIdx.x;
    int warp = tid >> 5, lane = tid & 31;
    int qr = lane >> 2, qc = lane & 3;
    int nBase = warp * 16;
    uint32_t tS_s = smem_u32(tS);
    int laneRow = (lane & 7) + (lane & 8);
    int laneColB = ((lane >> 4) & 1) * 16;
    uint32_t lmBase = tS_s + (uint32_t)laneRow * 272 + (uint32_t)laneColB;
    float* esumW = esum + warp * 128;

    unsigned bf[8][2][2];
#pragma unroll
    for (int c = 0; c < 8; c++) {
        int kb = c * 16;
#pragma unroll
        for (int ncl = 0; ncl < 2; ncl++) {
            int n = nBase + ncl * 8 + qr;
            bf[c][ncl][0] = h2_bits(__floats2half2_rn(
                __ldg(W2 + (kb + 2 * qc) * 128 + n), __ldg(W2 + (kb + 2 * qc + 1) * 128 + n)));
            bf[c][ncl][1] = h2_bits(__floats2half2_rn(
                __ldg(W2 + (kb + 2 * qc + 8) * 128 + n), __ldg(W2 + (kb + 2 * qc + 9) * 128 + n)));
        }
    }
    float bb0[2], bb1[2], w30[2], w31[2];
#pragma unroll
    for (int ncl = 0; ncl < 2; ncl++) {
        int c0 = nBase + ncl * 8 + qc * 2;
        bb0[ncl] = __ldg(b2 + c0); bb1[ncl] = __ldg(b2 + c0 + 1);
        w30[ncl] = __ldg(W3 + c0); w31[ncl] = __ldg(W3 + c0 + 1);
    }
    float b3v = __ldg(b3);
    if (tid < 64) b1h[tid] = h2_bits(__floats2half2_rn(__ldg(b1 + 2 * tid), __ldg(b1 + 2 * tid + 1)));
    __syncthreads();

    const __half2 hz = __floats2half2_rn(0.f, 0.f);
    int eloc = tid >> 1;
    int half_ = tid & 1;

    int sCur = 0, dCur = 0, vCur = 0;
    {
        int tile0 = blockIdx.x;
        if (tile0 < numTiles) {
            int e = tile0 * 128 + eloc;
            if (e < E) { sCur = ei[e]; dCur = ei[E + e]; vCur = 1; }
        }
    }

    for (int tile = blockIdx.x; tile < numTiles; tile += gridDim.x) {
        // phase 1 (no loop-top barrier needed: previous tile's tS reads were
        // fenced by the pre-epilogue sync; epilogue touches only esum/out)
        {
            uint4* trow4 = (uint4*)(tS + eloc * TS_HW + half_ * 32);
            if (vCur) {
                const uint4* ap = (const uint4*)(Ad + (size_t)sCur * 128) + half_ * 8;
                const uint4* bp = (const uint4*)(Bd + (size_t)dCur * 128) + half_ * 8;
                const uint4* cb = (const uint4*)b1h + half_ * 8;
#pragma unroll
                for (int j = 0; j < 8; j++) {
                    uint4 av = __ldg(ap + j);
                    uint4 bv = __ldg(bp + j);
                    uint4 cv = cb[j];
                    uint4 r;
                    r.x = h2_bits(__hmax2(__hadd2(__hadd2(bits_h2(av.x), bits_h2(bv.x)), bits_h2(cv.x)), hz));
                    r.y = h2_bits(__hmax2(__hadd2(__hadd2(bits_h2(av.y), bits_h2(bv.y)), bits_h2(cv.y)), hz));
                    r.z = h2_bits(__hmax2(__hadd2(__hadd2(bits_h2(av.z), bits_h2(bv.z)), bits_h2(cv.z)), hz));
                    r.w = h2_bits(__hmax2(__hadd2(__hadd2(bits_h2(av.w), bits_h2(bv.w)), bits_h2(cv.w)), hz));
                    trow4[j] = r;
                }
            } else {
                uint4 z4 = make_uint4(0u, 0u, 0u, 0u);
#pragma unroll
                for (int j = 0; j < 8; j++) trow4[j] = z4;
            }
        }
        __syncthreads();

        {
            int tNext = tile + gridDim.x;
            vCur = 0;
            if (tNext < numTiles) {
                int e = tNext * 128 + eloc;
                if (e < E) { sCur = ei[e]; dCur = ei[E + e]; vCur = 1; }
            }
        }

#pragma unroll 1
        for (int m = 0; m < 8; m++) {
            int r0 = m * 16;
            uint32_t rowAddr = lmBase + (uint32_t)r0 * 272;
            float acc[2][4];
            acc[0][0] = acc[0][1] = acc[0][2] = acc[0][3] = 0.f;
            acc[1][0] = acc[1][1] = acc[1][2] = acc[1][3] = 0.f;
#pragma unroll
            for (int c = 0; c < 8; c++) {
                unsigned a0, a1, a2, a3;
                asm volatile(
                    "ldmatrix.sync.aligned.m8n8.x4.shared.b16 {%0,%1,%2,%3}, [%4];"
                    : "=r"(a0), "=r"(a1), "=r"(a2), "=r"(a3)
                    : "r"(rowAddr + (uint32_t)c * 32));
                asm volatile(
                    "mma.sync.aligned.m16n8k16.row.col.f32.f16.f16.f32 "
                    "{%0,%1,%2,%3}, {%4,%5,%6,%7}, {%8,%9}, {%0,%1,%2,%3};"
                    : "+f"(acc[0][0]), "+f"(acc[0][1]), "+f"(acc[0][2]), "+f"(acc[0][3])
                    : "r"(a0), "r"(a1), "r"(a2), "r"(a3), "r"(bf[c][0][0]), "r"(bf[c][0][1]));
                asm volatile(
                    "mma.sync.aligned.m16n8k16.row.col.f32.f16.f16.f32 "
                    "{%0,%1,%2,%3}, {%4,%5,%6,%7}, {%8,%9}, {%0,%1,%2,%3};"
                    : "+f"(acc[1][0]), "+f"(acc[1][1]), "+f"(acc[1][2]), "+f"(acc[1][3])
                    : "r"(a0), "r"(a1), "r"(a2), "r"(a3), "r"(bf[c][1][0]), "r"(bf[c][1][1]));
            }
            float e0 = 0.f, e1 = 0.f;
#pragma unroll
            for (int ncl = 0; ncl < 2; ncl++) {
                e0 += fmaxf(acc[ncl][0] + bb0[ncl], 0.f) * w30[ncl]
                    + fmaxf(acc[ncl][1] + bb1[ncl], 0.f) * w31[ncl];
                e1 += fmaxf(acc[ncl][2] + bb0[ncl], 0.f) * w30[ncl]
                    + fmaxf(acc[ncl][3] + bb1[ncl], 0.f) * w31[ncl];
            }
            e0 += __shfl_xor_sync(0xffffffffu, e0, 1);
            e0 += __shfl_xor_sync(0xffffffffu, e0, 2);
            e1 += __shfl_xor_sync(0xffffffffu, e1, 1);
            e1 += __shfl_xor_sync(0xffffffffu, e1, 2);
            if (qc == 0) {
                esumW[r0 + qr] = e0;
                esumW[r0 + qr + 8] = e1;
            }
        }
        __syncthreads();

        if (tid < 128) {
            int e = tile * 128 + tid;
            if (e < E) {
                float s = esum[tid];
#pragma unroll
                for (int w = 1; w < 8; w++) s += esum[w * 128 + tid];
                out[e] = s + b3v;
            }
        }
    }
}

extern "C" void kernel_launch(void* const* d_in, const int* in_sizes, int n_in,
                              void* d_out, int out_size) {
    const int* node_ids = (const int*)d_in[0];
    const int* ei       = (const int*)d_in[1];
    const int* nei      = (const int*)d_in[2];
    const float* eattr  = (const float*)d_in[3];
    const float* emb    = (const float*)d_in[4];
    const float* W_in   = (const float*)d_in[5];
    const float* b_in   = (const float*)d_in[6];
    const float* W_out  = (const float*)d_in[7];
    const float* b_out  = (const float*)d_in[8];
    const float* W1     = (const float*)d_in[9];
    const float* b1     = (const float*)d_in[10];
    const float* W2     = (const float*)d_in[11];
    const float* b2     = (const float*)d_in[12];
    const float* W3     = (const float*)d_in[13];
    const float* b3     = (const float*)d_in[14];
    int N = in_sizes[0];
    int E = in_sizes[3];
    float* out = (float*)d_out;

    float *agg1, *x1, *x2;
    __half *embh, *h2h, *Ad, *Bd;
    int *off1, *off2;
    int2 *pair1, *pair2;
    cudaGetSymbolAddress((void**)&embh, g_embh);
    cudaGetSymbolAddress((void**)&agg1, g_agg1);
    cudaGetSymbolAddress((void**)&x1, g_x1);
    cudaGetSymbolAddress((void**)&h2h, g_h2h);
    cudaGetSymbolAddress((void**)&x2, g_x2);
    cudaGetSymbolAddress((void**)&Ad, g_Adec);
    cudaGetSymbolAddress((void**)&Bd, g_Bdec);
    cudaGetSymbolAddress((void**)&off1, g_off1);
    cudaGetSymbolAddress((void**)&off2, g_off2);
    cudaGetSymbolAddress((void**)&pair1, g_pair1);
    cudaGetSymbolAddress((void**)&pair2, g_pair2);

    const int T = 256;
    init_f2h_kernel<<<(N * 32 + T - 1) / T, T>>>(emb, embh, N, N * 32);
    deg_cnt_kernel<<<(E + T - 1) / T, T>>>(ei, eattr, nei, E);
    scan2_kernel<<<1, 1024>>>(N, E);
    fill_kernel<<<(E + T - 1) / T, T>>>(ei, nei, eattr, node_ids, E);

    int mBlocks = (N + 127) / 128;
    int smem_split = (128 * A_STU * 2 + 128 * W_STU * 2) * 4;
    cudaFuncSetAttribute((const void*)gemm_fp16_kernel<1, 0, 0, 0>,
                         cudaFuncAttributeMaxDynamicSharedMemorySize, smem_split);
    cudaFuncSetAttribute((const void*)gemm_fp16_kernel<1, 0, 0, 1>,
                         cudaFuncAttributeMaxDynamicSharedMemorySize, smem_split);
    cudaFuncSetAttribute((const void*)gemm_fp16_kernel<1, 1, 1, 1>,
                         cudaFuncAttributeMaxDynamicSharedMemorySize, smem_split);

    int gatherBlocks = (N * 16 + T - 1) / T;

    gather_f16_kernel<<<gatherBlocks, T>>>(embh, agg1, off1, pair1, N);
    gemm_fp16_kernel<1, 0, 0, 0><<<dim3(2, mBlocks), 256, smem_split>>>(
        agg1, W_in, x1, N, 128, 256, b_in, 1, nullptr, nullptr, nullptr);

    gemm_fp16_kernel<1, 0, 0, 1><<<dim3(1, mBlocks), 256, smem_split>>>(
        x1, W_out, h2h, N, 256, 128, nullptr, 0, nullptr, nullptr, nullptr);
    gather_f16_kernel<<<gatherBlocks, T>>>(h2h, x2, off2, pair2, N);

    gemm_fp16_kernel<1, 1, 1, 1><<<dim3(2, mBlocks), 256, smem_split>>>(
        x2, W1, Ad, N, 128, 128, nullptr, 0, b_out, W1 + 128 * 128, Bd);

    int numTiles = (E + 127) / 128;
    int smem_dec = (128 * TS_HW + 64 + 8 * 128) * 4;
    cudaFuncSetAttribute(decoder_fp16_kernel, cudaFuncAttributeMaxDynamicSharedMemorySize, smem_dec);
    int grid_dec = 4 * 148;
    if (grid_dec > numTiles) grid_dec = numTiles;
    decoder_fp16_kernel<<<grid_dec, 256, smem_dec>>>(Ad, Bd, ei, b1, W2, b2, W3, b3, out, E, numTiles);
}